// round 4
// baseline (speedup 1.0000x reference)
#include <cuda_runtime.h>
#include <cuda_bf16.h>

// Problem constants (fixed by the reference)
#define NN 4096
#define KK 32
#define DD 256
#define HH 128
#define GG 384   // 3*H

typedef unsigned long long ull;

// ---------------- device scratch (no allocations allowed) ----------------
static __device__ float4 g_wih0p[64 * GG];   // W_ih0 packed [k4][g] for k_xw0
static __device__ float  g_xw0[NN * GG];     // x @ W_ih0^T + b_ih0   (6.3 MB)
static __device__ int    g_sorted[NN];
static __device__ int    g_off[KK + 1];
static __device__ int    g_len[KK];
static __device__ float  g_emb[KK * HH];
static __device__ float  g_scores[NN];
static __device__ float  g_clusum[KK];

// ---------------- f32x2 packed-FMA helpers ----------------
static __device__ __forceinline__ ull ffma2(ull a, ull b, ull c) {
    ull d;
    asm("fma.rn.f32x2 %0, %1, %2, %3;" : "=l"(d) : "l"(a), "l"(b), "l"(c));
    return d;
}
static __device__ __forceinline__ float f2sum(ull v) {
    float a, b;
    asm("mov.b64 {%0, %1}, %2;" : "=f"(a), "=f"(b) : "l"(v));
    return a + b;
}
static __device__ __forceinline__ float sigmoidf_(float x) {
    return 1.0f / (1.0f + expf(-x));
}
static __device__ __forceinline__ unsigned mapa32(unsigned a, int r) {
    unsigned d;
    asm("mapa.shared::cluster.u32 %0, %1, %2;" : "=r"(d) : "r"(a), "r"(r));
    return d;
}
static __device__ __forceinline__ void stremote(unsigned a, float v) {
    asm volatile("st.shared::cluster.f32 [%0], %1;" :: "r"(a), "f"(v) : "memory");
}
static __device__ __forceinline__ void mbar_init(unsigned a, unsigned cnt) {
    asm volatile("mbarrier.init.shared.b64 [%0], %1;" :: "r"(a), "r"(cnt) : "memory");
}
static __device__ __forceinline__ void mbar_arrive_cluster(unsigned a) {
    asm volatile("mbarrier.arrive.release.cluster.shared::cluster.b64 _, [%0];"
                 :: "r"(a) : "memory");
}
static __device__ __forceinline__ void mbar_wait_parity(unsigned a, unsigned ph) {
    asm volatile(
        "{\n\t"
        ".reg .pred P;\n\t"
        "WL%=:\n\t"
        "mbarrier.try_wait.parity.acquire.cluster.shared::cta.b64 P, [%0], %1, 0x989680;\n\t"
        "@!P bra WL%=;\n\t"
        "}" :: "r"(a), "r"(ph) : "memory");
}
#define CLUSTER_ARRIVE() asm volatile("barrier.cluster.arrive.aligned;" ::: "memory")
#define CLUSTER_WAIT()   asm volatile("barrier.cluster.wait.aligned;"   ::: "memory")

// ---------------- kernel: cluster ordering (stable, parallel) ----------------
__global__ void k_setup(const int* __restrict__ labels) {
    __shared__ int ls[NN];
    __shared__ int cnt[8][KK];
    __shared__ int soff[8][KK];
    int t = threadIdx.x;                 // 256 threads
    for (int i = t; i < NN; i += 256) ls[i] = labels[i];
    __syncthreads();
    int w = t >> 5, k = t & 31;
    {
        int c = 0;
        const int4* p = (const int4*)(ls + w * 512);
        for (int ii = 0; ii < 128; ++ii) {
            int4 v = p[ii];
            c += (v.x == k) + (v.y == k) + (v.z == k) + (v.w == k);
        }
        cnt[w][k] = c;
    }
    __syncthreads();
    if (w == 0) {
        int tot = 0;
        #pragma unroll
        for (int s = 0; s < 8; ++s) tot += cnt[s][k];
        g_len[k] = tot;
        int v = tot;
        #pragma unroll
        for (int d = 1; d < 32; d <<= 1) {
            int y = __shfl_up_sync(0xffffffffu, v, d);
            if (k >= d) v += y;
        }
        int off = v - tot;
        g_off[k] = off;
        if (k == 31) g_off[32] = off + tot;
        int run = off;
        #pragma unroll
        for (int s = 0; s < 8; ++s) { soff[s][k] = run; run += cnt[s][k]; }
    }
    __syncthreads();
    {
        int c = soff[w][k];
        const int4* p = (const int4*)(ls + w * 512);
        for (int ii = 0; ii < 128; ++ii) {
            int4 v = p[ii];
            int b = w * 512 + ii * 4;
            if (v.x == k) g_sorted[c++] = b;
            if (v.y == k) g_sorted[c++] = b + 1;
            if (v.z == k) g_sorted[c++] = b + 2;
            if (v.w == k) g_sorted[c++] = b + 3;
        }
    }
}

// ---------------- kernel: pack W_ih0 [g][k] -> [k4][g] float4 ----------------
__global__ void k_pack(const float* __restrict__ wih0) {
    int k4 = blockIdx.x;        // 0..63
    int g  = threadIdx.x;       // 0..383
    const float* row = wih0 + (size_t)g * DD + k4 * 4;
    g_wih0p[k4 * GG + g] = make_float4(row[0], row[1], row[2], row[3]);
}

// ---------------- kernel: xw0 = x @ W_ih0^T + b_ih0 ----------------
__global__ void __launch_bounds__(384) k_xw0(const float* __restrict__ x,
                                             const float* __restrict__ b_ih0) {
    __shared__ __align__(16) float xs[16 * DD];   // 16 KB
    int r0 = blockIdx.x * 16;
    {
        const float4* xsrc = reinterpret_cast<const float4*>(x + (size_t)r0 * DD);
        float4* xd = reinterpret_cast<float4*>(xs);
        for (int i = threadIdx.x; i < 16 * DD / 4; i += 384) xd[i] = xsrc[i];
    }
    __syncthreads();
    int g = threadIdx.x;
    ull acc[16];
    #pragma unroll
    for (int s = 0; s < 16; ++s) acc[s] = 0ull;
    const ulonglong2* W = reinterpret_cast<const ulonglong2*>(g_wih0p) + g;
    #pragma unroll 8
    for (int k4 = 0; k4 < 64; ++k4) {
        ulonglong2 w = W[k4 * GG];
        #pragma unroll
        for (int s = 0; s < 16; ++s) {
            ulonglong2 xv = *reinterpret_cast<const ulonglong2*>(&xs[s * DD + k4 * 4]);
            acc[s] = ffma2(w.x, xv.x, acc[s]);
            acc[s] = ffma2(w.y, xv.y, acc[s]);
        }
    }
    float bi = b_ih0[g];
    #pragma unroll
    for (int s = 0; s < 16; ++s)
        g_xw0[(size_t)(r0 + s) * GG + g] = f2sum(acc[s]) + bi;
}

// ---------------- kernel: GRU recurrence ----------------
// 32 CGAs x 4 CTAs. Each CTA holds 96/384 gate rows of Whh0/Whh1/Wih1 in
// registers. After the matvec reduction, each CTA broadcasts its 288
// gate-preactivations (bias folded) to ALL CTAs' staging buffers; every CTA
// then computes the full gate update LOCALLY (redundantly, deterministically).
// Sync = one DSMEM mbarrier phase per step (no barrier.cluster, no L1 flush).
// h is local/single-buffered; staging double-buffered by parity.
__global__ void __cluster_dims__(4, 1, 1) __launch_bounds__(384, 1)
k_rec(const float* __restrict__ Whh0, const float* __restrict__ Wih1,
      const float* __restrict__ Whh1,
      const float* __restrict__ b_ih0, const float* __restrict__ b_hh0,
      const float* __restrict__ b_ih1, const float* __restrict__ b_hh1) {
    __shared__ __align__(16) float h1s[HH];
    __shared__ __align__(16) float h2s[HH];
    __shared__ float stg[2][3][GG];                 // [parity][hw0|hw1|xw1][row]
    __shared__ __align__(16) float stage[48 * 132]; // weight-load staging
    __shared__ __align__(8) unsigned long long mbar;

    const int t = threadIdx.x;
    const int c = blockIdx.x >> 2;
    int rank_;
    asm("mov.u32 %0, %%cluster_ctarank;" : "=r"(rank_));
    const int rank = rank_;

    const int rr = t >> 2;        // 0..95: output row within this CTA's slice
    const int q  = t & 3;         // k-quarter (32 values each)
    const int mrow = (rr >> 5) * HH + 32 * rank + (rr & 31);  // global gate row

    float bh0 = b_hh0[mrow], bh1 = b_hh1[mrow], bi1 = b_ih1[mrow];

    if (t < HH) { h1s[t] = 0.f; h2s[t] = 0.f; }
    if (t == 0) mbar_init((unsigned)__cvta_generic_to_shared(&mbar), 48u);

    // ---- load per-thread weight slices into registers (coalesced via smem stage)
    ulonglong2 wA[8], wB[8], wC[8];
#define LOADW(SRC, DST)                                                           \
    for (int hrow = 0; hrow < 2; ++hrow) {                                        \
        _Pragma("unroll")                                                         \
        for (int qq = 0; qq < 4; ++qq) {                                          \
            int f4i = t * 4 + qq;                                                 \
            int rline = f4i >> 5, c4 = f4i & 31;                                  \
            int rr2 = hrow * 48 + rline;                                          \
            int m2 = (rr2 >> 5) * HH + 32 * rank + (rr2 & 31);                    \
            *(float4*)&stage[rline * 132 + c4 * 4] =                              \
                *(const float4*)(SRC + (size_t)m2 * HH + c4 * 4);                 \
        }                                                                         \
        __syncthreads();                                                          \
        if (rr >= hrow * 48 && rr < hrow * 48 + 48) {                             \
            int rline = rr - hrow * 48;                                           \
            _Pragma("unroll")                                                     \
            for (int i = 0; i < 8; ++i)                                           \
                DST[i] = *(const ulonglong2*)&stage[rline * 132 + q * 32 + i * 4];\
        }                                                                         \
        __syncthreads();                                                          \
    }
    LOADW(Whh0, wA)
    LOADW(Whh1, wB)
    LOADW(Wih1, wC)
#undef LOADW

    // ---- gate-input prefetch state (full 128-wide, every CTA)
    const int len = g_len[c];
    const int off = g_off[c];
    const int len_e = max(len, 1);
    float xr_c = 0.f, xz_c = 0.f, xn_c = 0.f;
    int idxA = 0;
    if (t < HH) {
        if (len > 0) {
            int i0 = g_sorted[off];
            const float* p = g_xw0 + (size_t)i0 * GG;
            xr_c = p[t]; xz_c = p[HH + t]; xn_c = p[2 * HH + t];
        } else {  // empty cluster: single step with x = 0 (xw = b_ih0)
            xr_c = b_ih0[t]; xz_c = b_ih0[HH + t]; xn_c = b_ih0[2 * HH + t];
        }
        if (len > 1) idxA = g_sorted[off + 1];
    }

    // ---- DSMEM addresses (all 4 ranks, self included)
    unsigned ss = (unsigned)__cvta_generic_to_shared(&stg[0][0][0]);
    unsigned mb = (unsigned)__cvta_generic_to_shared(&mbar);
    unsigned pstg[4], pmb[4];
    #pragma unroll
    for (int r = 0; r < 4; ++r) { pstg[r] = mapa32(ss, r); pmb[r] = mapa32(mb, r); }

    CLUSTER_ARRIVE();
    CLUSTER_WAIT();

    for (int it = 0; it <= len_e; ++it) {
        const int p = it & 1;
        // ---- three matvecs from register weights + local smem h
        ull a0x = 0, a0y = 0, a1x = 0, a1y = 0, a2x = 0, a2y = 0;
        const ulonglong2* h1p = (const ulonglong2*)&h1s[0] + q * 8;
        const ulonglong2* h2p = (const ulonglong2*)&h2s[0] + q * 8;
        #pragma unroll
        for (int i = 0; i < 8; ++i) {
            ulonglong2 hv1 = h1p[i];
            a0x = ffma2(wA[i].x, hv1.x, a0x); a0y = ffma2(wA[i].y, hv1.y, a0y);
            a2x = ffma2(wC[i].x, hv1.x, a2x); a2y = ffma2(wC[i].y, hv1.y, a2y);
            ulonglong2 hv2 = h2p[i];
            a1x = ffma2(wB[i].x, hv2.x, a1x); a1y = ffma2(wB[i].y, hv2.y, a1y);
        }
        float s0 = f2sum(a0x) + f2sum(a0y);
        float s1 = f2sum(a1x) + f2sum(a1y);
        float s2 = f2sum(a2x) + f2sum(a2y);
        s0 += __shfl_xor_sync(0xffffffffu, s0, 1); s0 += __shfl_xor_sync(0xffffffffu, s0, 2);
        s1 += __shfl_xor_sync(0xffffffffu, s1, 1); s1 += __shfl_xor_sync(0xffffffffu, s1, 2);
        s2 += __shfl_xor_sync(0xffffffffu, s2, 1); s2 += __shfl_xor_sync(0xffffffffu, s2, 2);

        // ---- broadcast gate-preactivations (bias folded) to all 4 CTAs
        float v = (q == 0) ? (s0 + bh0) : ((q == 1) ? (s1 + bh1) : (s2 + bi1));
        unsigned soff = (unsigned)((((p * 3 + q) * GG) + mrow) * 4);
        if (q < 3) {
            stremote(pstg[0] + soff, v); stremote(pstg[1] + soff, v);
            stremote(pstg[2] + soff, v); stremote(pstg[3] + soff, v);
        }
        __syncwarp();
        if ((t & 31) == 0) {
            mbar_arrive_cluster(pmb[0]); mbar_arrive_cluster(pmb[1]);
            mbar_arrive_cluster(pmb[2]); mbar_arrive_cluster(pmb[3]);
        }
        mbar_wait_parity(mb, (unsigned)p);

        // ---- full gate update, computed locally in every CTA
        if (t < HH) {
            if (it < len_e) {
                float r = sigmoidf_(xr_c + stg[p][0][t]);
                float z = sigmoidf_(xz_c + stg[p][0][HH + t]);
                float n = tanhf(xn_c + r * stg[p][0][2 * HH + t]);
                h1s[t] = (1.0f - z) * n + z * h1s[t];
            }
            // prefetch next sentence's xw0 row (hidden under next matvec+wait)
            if (it + 1 < len) {
                const float* pp = g_xw0 + (size_t)idxA * GG;
                xr_c = pp[t]; xz_c = pp[HH + t]; xn_c = pp[2 * HH + t];
            }
            if (it + 2 < len) idxA = g_sorted[off + it + 2];
        } else if (t < 2 * HH && it >= 1) {
            int j = t - HH;
            float r = sigmoidf_(stg[p][2][j] + stg[p][1][j]);
            float z = sigmoidf_(stg[p][2][HH + j] + stg[p][1][HH + j]);
            float n = tanhf(stg[p][2][2 * HH + j] + r * stg[p][1][2 * HH + j]);
            h2s[j] = (1.0f - z) * n + z * h2s[j];
        }
        __syncthreads();
    }

    if (rank == 0 && t < HH) g_emb[c * HH + t] = h2s[t];
}

// ---------------- kernel: per-sentence tanh scores (weight-norm fused) ----------------
__global__ void __launch_bounds__(128) k_score(const float* __restrict__ x,
                                               const int* __restrict__ labels,
                                               const float* __restrict__ lin_v,
                                               const float* __restrict__ lin_g,
                                               const float* __restrict__ lin_b) {
    __shared__ __align__(16) float wns[GG];
    __shared__ __align__(16) float embs[KK][132];  // padded
    __shared__ float redw[4];
    int t = threadIdx.x;
    float v0 = lin_v[t], v1 = lin_v[HH + t], v2 = lin_v[2 * HH + t];
    float ss = v0 * v0 + v1 * v1 + v2 * v2;
    #pragma unroll
    for (int d = 16; d >= 1; d >>= 1) ss += __shfl_xor_sync(0xffffffffu, ss, d);
    if ((t & 31) == 0) redw[t >> 5] = ss;
    __syncthreads();
    float scale = lin_g[0] / sqrtf(redw[0] + redw[1] + redw[2] + redw[3]);
    wns[t] = v0 * scale; wns[HH + t] = v1 * scale; wns[2 * HH + t] = v2 * scale;
    for (int i = t; i < KK * HH; i += 128) embs[i >> 7][i & 127] = g_emb[i];
    __syncthreads();
    int i = blockIdx.x * 128 + t;
    int lab = labels[i];
    const float4* xr = reinterpret_cast<const float4*>(x) + (size_t)i * (DD / 4);
    float acc = 0.f;
    #pragma unroll 8
    for (int k4 = 0; k4 < DD / 4; ++k4) {
        float4 xv = xr[k4];
        float4 wv = *reinterpret_cast<const float4*>(&wns[k4 * 4]);
        acc = fmaf(xv.x, wv.x, acc); acc = fmaf(xv.y, wv.y, acc);
        acc = fmaf(xv.z, wv.z, acc); acc = fmaf(xv.w, wv.w, acc);
    }
    #pragma unroll 8
    for (int k4 = 0; k4 < HH / 4; ++k4) {
        float4 ev = *reinterpret_cast<const float4*>(&embs[lab][k4 * 4]);
        float4 wv = *reinterpret_cast<const float4*>(&wns[DD + k4 * 4]);
        acc = fmaf(ev.x, wv.x, acc); acc = fmaf(ev.y, wv.y, acc);
        acc = fmaf(ev.z, wv.z, acc); acc = fmaf(ev.w, wv.w, acc);
    }
    g_scores[i] = tanhf(acc + lin_b[0]);
}

// ---------------- kernel: deterministic per-cluster score sums ----------------
__global__ void __launch_bounds__(128) k_clusum() {
    __shared__ float red[128];
    int k = blockIdx.x;
    int len = g_len[k], off = g_off[k];
    float s = 0.f;
    for (int t = threadIdx.x; t < len; t += 128) s += g_scores[g_sorted[off + t]];
    red[threadIdx.x] = s;
    __syncthreads();
    #pragma unroll
    for (int d = 64; d >= 1; d >>= 1) {
        if (threadIdx.x < d) red[threadIdx.x] += red[threadIdx.x + d];
        __syncthreads();
    }
    if (threadIdx.x == 0) g_clusum[k] = red[0];
}

// ---------------- kernel: final blend ----------------
__global__ void k_final(const int* __restrict__ labels, float* __restrict__ out) {
    int i = blockIdx.x * blockDim.x + threadIdx.x;
    if (i >= NN) return;
    const float INV = 0.0625f;  // 1 / 4096^(1/3)
    float sal = g_scores[i] / g_clusum[labels[i]];
    float pos = fmaxf(0.5f, expf(-((float)(i + 1)) * INV));
    out[i] = 0.5f * sal + 0.5f * pos;
}

// ---------------- launch ----------------
extern "C" void kernel_launch(void* const* d_in, const int* in_sizes, int n_in,
                              void* d_out, int out_size) {
    const float* x      = (const float*)d_in[0];
    const int*   labels = (const int*)d_in[1];
    const float* W_ih0  = (const float*)d_in[2];
    const float* W_hh0  = (const float*)d_in[3];
    const float* b_ih0  = (const float*)d_in[4];
    const float* b_hh0  = (const float*)d_in[5];
    const float* W_ih1  = (const float*)d_in[6];
    const float* W_hh1  = (const float*)d_in[7];
    const float* b_ih1  = (const float*)d_in[8];
    const float* b_hh1  = (const float*)d_in[9];
    const float* lin_v  = (const float*)d_in[10];
    const float* lin_g  = (const float*)d_in[11];
    const float* lin_b  = (const float*)d_in[12];
    float* out = (float*)d_out;

    k_setup<<<1, 256>>>(labels);
    k_pack<<<64, 384>>>(W_ih0);
    k_xw0<<<NN / 16, 384>>>(x, b_ih0);
    k_rec<<<128, 384>>>(W_hh0, W_ih1, W_hh1, b_ih0, b_hh0, b_ih1, b_hh1);
    k_score<<<NN / 128, 128>>>(x, labels, lin_v, lin_g, lin_b);
    k_clusum<<<KK, 128>>>();
    k_final<<<16, 256>>>(labels, out);
}

// round 5
// speedup vs baseline: 1.1007x; 1.1007x over previous
#include <cuda_runtime.h>
#include <cuda_bf16.h>

// Problem constants (fixed by the reference)
#define NN 4096
#define KK 32
#define DD 256
#define HH 128
#define GG 384   // 3*H

typedef unsigned long long ull;

// ---------------- device scratch (no allocations allowed) ----------------
static __device__ float4 g_wih0p[64 * GG];   // W_ih0 packed [k4][g] for k_xw0
static __device__ float  g_xw0[NN * GG];     // x @ W_ih0^T + b_ih0   (6.3 MB)
static __device__ int    g_sorted[NN];
static __device__ int    g_off[KK + 1];
static __device__ int    g_len[KK];
static __device__ float  g_emb[KK * HH];
static __device__ float  g_scores[NN];

// ---------------- f32x2 packed-FMA helpers ----------------
static __device__ __forceinline__ ull ffma2(ull a, ull b, ull c) {
    ull d;
    asm("fma.rn.f32x2 %0, %1, %2, %3;" : "=l"(d) : "l"(a), "l"(b), "l"(c));
    return d;
}
static __device__ __forceinline__ float f2sum(ull v) {
    float a, b;
    asm("mov.b64 {%0, %1}, %2;" : "=f"(a), "=f"(b) : "l"(v));
    return a + b;
}
// fast gates via MUFU (ex2/rcp approx): ~1e-6 rel err, far inside 1e-3 budget
static __device__ __forceinline__ float ex2_(float x) {
    float y; asm("ex2.approx.f32 %0, %1;" : "=f"(y) : "f"(x)); return y;
}
static __device__ __forceinline__ float rcp_(float x) {
    float y; asm("rcp.approx.f32 %0, %1;" : "=f"(y) : "f"(x)); return y;
}
#define L2E 1.4426950408889634f
static __device__ __forceinline__ float fast_sigmoid(float x) {
    return rcp_(1.0f + ex2_(-x * L2E));          // large |x| saturates correctly
}
static __device__ __forceinline__ float fast_tanh(float x) {
    x = fminf(x, 20.0f);                         // avoid inf/inf
    float e = ex2_(x * (2.0f * L2E));
    return (e - 1.0f) * rcp_(e + 1.0f);
}
static __device__ __forceinline__ unsigned mapa32(unsigned a, int r) {
    unsigned d;
    asm("mapa.shared::cluster.u32 %0, %1, %2;" : "=r"(d) : "r"(a), "r"(r));
    return d;
}
static __device__ __forceinline__ void stremote(unsigned a, float v) {
    asm volatile("st.shared::cluster.f32 [%0], %1;" :: "r"(a), "f"(v) : "memory");
}
static __device__ __forceinline__ void mbar_init(unsigned a, unsigned cnt) {
    asm volatile("mbarrier.init.shared.b64 [%0], %1;" :: "r"(a), "r"(cnt) : "memory");
}
static __device__ __forceinline__ void mbar_arrive_cluster(unsigned a) {
    asm volatile("mbarrier.arrive.release.cluster.shared::cluster.b64 _, [%0];"
                 :: "r"(a) : "memory");
}
static __device__ __forceinline__ void mbar_wait_parity(unsigned a, unsigned ph) {
    asm volatile(
        "{\n\t"
        ".reg .pred P;\n\t"
        "WL%=:\n\t"
        "mbarrier.try_wait.parity.acquire.cluster.shared::cta.b64 P, [%0], %1, 0x989680;\n\t"
        "@!P bra WL%=;\n\t"
        "}" :: "r"(a), "r"(ph) : "memory");
}
#define CLUSTER_ARRIVE() asm volatile("barrier.cluster.arrive.aligned;" ::: "memory")
#define CLUSTER_WAIT()   asm volatile("barrier.cluster.wait.aligned;"   ::: "memory")

// ---------------- kernel: cluster ordering (stable, parallel) ----------------
__global__ void k_setup(const int* __restrict__ labels) {
    __shared__ int ls[NN];
    __shared__ int cnt[8][KK];
    __shared__ int soff[8][KK];
    int t = threadIdx.x;                 // 256 threads
    for (int i = t; i < NN; i += 256) ls[i] = labels[i];
    __syncthreads();
    int w = t >> 5, k = t & 31;
    {
        int c = 0;
        const int4* p = (const int4*)(ls + w * 512);
        for (int ii = 0; ii < 128; ++ii) {
            int4 v = p[ii];
            c += (v.x == k) + (v.y == k) + (v.z == k) + (v.w == k);
        }
        cnt[w][k] = c;
    }
    __syncthreads();
    if (w == 0) {
        int tot = 0;
        #pragma unroll
        for (int s = 0; s < 8; ++s) tot += cnt[s][k];
        g_len[k] = tot;
        int v = tot;
        #pragma unroll
        for (int d = 1; d < 32; d <<= 1) {
            int y = __shfl_up_sync(0xffffffffu, v, d);
            if (k >= d) v += y;
        }
        int off = v - tot;
        g_off[k] = off;
        if (k == 31) g_off[32] = off + tot;
        int run = off;
        #pragma unroll
        for (int s = 0; s < 8; ++s) { soff[s][k] = run; run += cnt[s][k]; }
    }
    __syncthreads();
    {
        int c = soff[w][k];
        const int4* p = (const int4*)(ls + w * 512);
        for (int ii = 0; ii < 128; ++ii) {
            int4 v = p[ii];
            int b = w * 512 + ii * 4;
            if (v.x == k) g_sorted[c++] = b;
            if (v.y == k) g_sorted[c++] = b + 1;
            if (v.z == k) g_sorted[c++] = b + 2;
            if (v.w == k) g_sorted[c++] = b + 3;
        }
    }
}

// ---------------- kernel: pack W_ih0 [g][k] -> [k4][g] float4 ----------------
__global__ void k_pack(const float* __restrict__ wih0) {
    int k4 = blockIdx.x;        // 0..63
    int g  = threadIdx.x;       // 0..383
    const float* row = wih0 + (size_t)g * DD + k4 * 4;
    g_wih0p[k4 * GG + g] = make_float4(row[0], row[1], row[2], row[3]);
}

// ---------------- kernel: xw0 = x @ W_ih0^T + b_ih0 ----------------
__global__ void __launch_bounds__(384) k_xw0(const float* __restrict__ x,
                                             const float* __restrict__ b_ih0) {
    __shared__ __align__(16) float xs[16 * DD];   // 16 KB
    int r0 = blockIdx.x * 16;
    {
        const float4* xsrc = reinterpret_cast<const float4*>(x + (size_t)r0 * DD);
        float4* xd = reinterpret_cast<float4*>(xs);
        for (int i = threadIdx.x; i < 16 * DD / 4; i += 384) xd[i] = xsrc[i];
    }
    __syncthreads();
    int g = threadIdx.x;
    ull acc[16];
    #pragma unroll
    for (int s = 0; s < 16; ++s) acc[s] = 0ull;
    const ulonglong2* W = reinterpret_cast<const ulonglong2*>(g_wih0p) + g;
    #pragma unroll 8
    for (int k4 = 0; k4 < 64; ++k4) {
        ulonglong2 w = W[k4 * GG];
        #pragma unroll
        for (int s = 0; s < 16; ++s) {
            ulonglong2 xv = *reinterpret_cast<const ulonglong2*>(&xs[s * DD + k4 * 4]);
            acc[s] = ffma2(w.x, xv.x, acc[s]);
            acc[s] = ffma2(w.y, xv.y, acc[s]);
        }
    }
    float bi = b_ih0[g];
    #pragma unroll
    for (int s = 0; s < 16; ++s)
        g_xw0[(size_t)(r0 + s) * GG + g] = f2sum(acc[s]) + bi;
}

// ---------------- kernel: GRU recurrence ----------------
// 32 CGAs x 4 CTAs. Each CTA holds 96/384 gate rows of Whh0/Whh1/Wih1 in
// registers; gates computed on the CTA's own 32-wide hidden slice; only the
// 2x32 NEW h values cross CTAs (coalesced DSMEM stores). Sync = one DSMEM
// mbarrier phase per step (count=8: 2 gate warps x 4 CTAs), replacing
// barrier.cluster (no UCGABAR_WAIT, no per-step L1D flush).
// h double-buffered by parity; layer 1 lags layer 0 by one step.
__global__ void __cluster_dims__(4, 1, 1) __launch_bounds__(384, 1)
k_rec(const float* __restrict__ Whh0, const float* __restrict__ Wih1,
      const float* __restrict__ Whh1,
      const float* __restrict__ b_ih0, const float* __restrict__ b_hh0,
      const float* __restrict__ b_ih1, const float* __restrict__ b_hh1) {
    __shared__ __align__(16) float h1s[2][HH];
    __shared__ __align__(16) float h2s[2][HH];
    __shared__ float hw0s[96], hw1s[96], xw1s[96];
    __shared__ __align__(16) float stage[48 * 132]; // weight-load staging
    __shared__ __align__(8) unsigned long long mbar;

    const int t = threadIdx.x;
    const int c = blockIdx.x >> 2;
    int rank_;
    asm("mov.u32 %0, %%cluster_ctarank;" : "=r"(rank_));
    const int rank = rank_;

    const int rr = t >> 2;        // 0..95: output row within this CTA's slice
    const int q  = t & 3;         // k-quarter (32 values each)
    const int mrow = (rr >> 5) * HH + 32 * rank + (rr & 31);  // global gate row

    float bh0 = b_hh0[mrow], bh1 = b_hh1[mrow], bi1 = b_ih1[mrow];

    if (t < HH) { h1s[0][t] = 0.f; h1s[1][t] = 0.f; h2s[0][t] = 0.f; h2s[1][t] = 0.f; }
    if (t == 0) mbar_init((unsigned)__cvta_generic_to_shared(&mbar), 8u);

    // ---- load per-thread weight slices into registers (coalesced via smem stage)
    ulonglong2 wA[8], wB[8], wC[8];
#define LOADW(SRC, DST)                                                           \
    for (int hrow = 0; hrow < 2; ++hrow) {                                        \
        _Pragma("unroll")                                                         \
        for (int qq = 0; qq < 4; ++qq) {                                          \
            int f4i = t * 4 + qq;                                                 \
            int rline = f4i >> 5, c4 = f4i & 31;                                  \
            int rr2 = hrow * 48 + rline;                                          \
            int m2 = (rr2 >> 5) * HH + 32 * rank + (rr2 & 31);                    \
            *(float4*)&stage[rline * 132 + c4 * 4] =                              \
                *(const float4*)(SRC + (size_t)m2 * HH + c4 * 4);                 \
        }                                                                         \
        __syncthreads();                                                          \
        if (rr >= hrow * 48 && rr < hrow * 48 + 48) {                             \
            int rline = rr - hrow * 48;                                           \
            _Pragma("unroll")                                                     \
            for (int i = 0; i < 8; ++i)                                           \
                DST[i] = *(const ulonglong2*)&stage[rline * 132 + q * 32 + i * 4];\
        }                                                                         \
        __syncthreads();                                                          \
    }
    LOADW(Whh0, wA)
    LOADW(Whh1, wB)
    LOADW(Wih1, wC)
#undef LOADW

    // ---- gate-thread input prefetch state (32-wide slice, warp 0 only)
    const int len = g_len[c];
    const int off = g_off[c];
    const int len_e = max(len, 1);
    float xr_c = 0.f, xz_c = 0.f, xn_c = 0.f;
    int idxA = 0;
    if (t < 32) {
        int j = 32 * rank + t;
        if (len > 0) {
            int i0 = g_sorted[off];
            const float* p = g_xw0 + (size_t)i0 * GG;
            xr_c = p[j]; xz_c = p[HH + j]; xn_c = p[2 * HH + j];
        } else {  // empty cluster: single step with x = 0 (xw = b_ih0)
            xr_c = b_ih0[j]; xz_c = b_ih0[HH + j]; xn_c = b_ih0[2 * HH + j];
        }
        if (len > 1) idxA = g_sorted[off + 1];
    }

    // ---- DSMEM addresses
    unsigned h1b = (unsigned)__cvta_generic_to_shared(&h1s[0][0]);
    unsigned h2b = (unsigned)__cvta_generic_to_shared(&h2s[0][0]);
    unsigned mb  = (unsigned)__cvta_generic_to_shared(&mbar);
    unsigned ph1[3], ph2[3], pmb[4];
    {
        int pi = 0;
        #pragma unroll
        for (int rp = 0; rp < 4; ++rp) {
            pmb[rp] = mapa32(mb, rp);
            if (rp != rank) { ph1[pi] = mapa32(h1b, rp); ph2[pi] = mapa32(h2b, rp); ++pi; }
        }
    }

    CLUSTER_ARRIVE();   // once: mbarrier init + zeroed h visible cluster-wide
    CLUSTER_WAIT();

    // Invariant at iteration `it` (p = it&1): h1s[p] = h1 after `it` layer-0
    // steps; h2s[p] = h2 after (it-1) layer-1 steps.
    for (int it = 0; it <= len_e; ++it) {
        const int p = it & 1;
        // ---- three matvecs from register weights + local smem h
        ull a0x = 0, a0y = 0, a1x = 0, a1y = 0, a2x = 0, a2y = 0;
        const ulonglong2* h1p = (const ulonglong2*)&h1s[p][0] + q * 8;
        const ulonglong2* h2p = (const ulonglong2*)&h2s[p][0] + q * 8;
        #pragma unroll
        for (int i = 0; i < 8; ++i) {
            ulonglong2 hv1 = h1p[i];
            a0x = ffma2(wA[i].x, hv1.x, a0x); a0y = ffma2(wA[i].y, hv1.y, a0y);
            a2x = ffma2(wC[i].x, hv1.x, a2x); a2y = ffma2(wC[i].y, hv1.y, a2y);
            ulonglong2 hv2 = h2p[i];
            a1x = ffma2(wB[i].x, hv2.x, a1x); a1y = ffma2(wB[i].y, hv2.y, a1y);
        }
        float s0 = f2sum(a0x) + f2sum(a0y);
        float s1 = f2sum(a1x) + f2sum(a1y);
        float s2 = f2sum(a2x) + f2sum(a2y);
        s0 += __shfl_xor_sync(0xffffffffu, s0, 1); s0 += __shfl_xor_sync(0xffffffffu, s0, 2);
        s1 += __shfl_xor_sync(0xffffffffu, s1, 1); s1 += __shfl_xor_sync(0xffffffffu, s1, 2);
        s2 += __shfl_xor_sync(0xffffffffu, s2, 1); s2 += __shfl_xor_sync(0xffffffffu, s2, 2);
        if (q == 0)      hw0s[rr] = s0 + bh0;   // Whh0 @ h1
        else if (q == 1) hw1s[rr] = s1 + bh1;   // Whh1 @ h2
        else if (q == 2) xw1s[rr] = s2 + bi1;   // Wih1 @ h1
        __syncthreads();   // hw ready AND all warps done reading h[p]

        if (t < 64) {
            // ---- layer-0 gate (warp 0): h1[it] from h1[it-1]
            if (t < 32) {
                if (it < len_e) {
                    int j = 32 * rank + t;
                    float r = fast_sigmoid(xr_c + hw0s[t]);
                    float z = fast_sigmoid(xz_c + hw0s[32 + t]);
                    float n = fast_tanh(xn_c + r * hw0s[64 + t]);
                    float hn = (1.0f - z) * n + z * h1s[p][j];
                    h1s[p ^ 1][j] = hn;
                    unsigned o = (unsigned)(((p ^ 1) * HH + j) * 4);
                    stremote(ph1[0] + o, hn); stremote(ph1[1] + o, hn); stremote(ph1[2] + o, hn);
                }
            }
            // ---- layer-1 gate, lagged (warp 1): h2[it-1]
            else if (it >= 1) {
                int j2 = t - 32;
                int j = 32 * rank + j2;
                float r = fast_sigmoid(xw1s[j2] + hw1s[j2]);
                float z = fast_sigmoid(xw1s[32 + j2] + hw1s[32 + j2]);
                float n = fast_tanh(xw1s[64 + j2] + r * hw1s[64 + j2]);
                float hn = (1.0f - z) * n + z * h2s[p][j];
                h2s[p ^ 1][j] = hn;
                unsigned o = (unsigned)(((p ^ 1) * HH + j) * 4);
                stremote(ph2[0] + o, hn); stremote(ph2[1] + o, hn); stremote(ph2[2] + o, hn);
            }
            __syncwarp();
            if ((t & 31) == 0) {   // one release-arrive per gate warp per CTA
                mbar_arrive_cluster(pmb[0]); mbar_arrive_cluster(pmb[1]);
                mbar_arrive_cluster(pmb[2]); mbar_arrive_cluster(pmb[3]);
            }
        }
        // ---- prefetch next sentence's xw0 slice (overlaps the wait)
        if (t < 32) {
            if (it + 1 < len) {
                const float* pp = g_xw0 + (size_t)idxA * GG;
                int j = 32 * rank + t;
                xr_c = pp[j]; xz_c = pp[HH + j]; xn_c = pp[2 * HH + j];
            }
            if (it + 2 < len) idxA = g_sorted[off + it + 2];
        }
        mbar_wait_parity(mb, (unsigned)p);
    }

    if (rank == 0 && t < HH) g_emb[c * HH + t] = h2s[(len_e + 1) & 1][t];
}

// ---------------- kernel: per-sentence tanh scores (weight-norm fused) ----------------
__global__ void __launch_bounds__(128) k_score(const float* __restrict__ x,
                                               const int* __restrict__ labels,
                                               const float* __restrict__ lin_v,
                                               const float* __restrict__ lin_g,
                                               const float* __restrict__ lin_b) {
    __shared__ __align__(16) float wns[GG];
    __shared__ __align__(16) float embs[KK][132];  // padded
    __shared__ float redw[4];
    int t = threadIdx.x;
    float v0 = lin_v[t], v1 = lin_v[HH + t], v2 = lin_v[2 * HH + t];
    float ss = v0 * v0 + v1 * v1 + v2 * v2;
    #pragma unroll
    for (int d = 16; d >= 1; d >>= 1) ss += __shfl_xor_sync(0xffffffffu, ss, d);
    if ((t & 31) == 0) redw[t >> 5] = ss;
    __syncthreads();
    float scale = lin_g[0] / sqrtf(redw[0] + redw[1] + redw[2] + redw[3]);
    wns[t] = v0 * scale; wns[HH + t] = v1 * scale; wns[2 * HH + t] = v2 * scale;
    for (int i = t; i < KK * HH; i += 128) embs[i >> 7][i & 127] = g_emb[i];
    __syncthreads();
    int i = blockIdx.x * 128 + t;
    int lab = labels[i];
    const float4* xr = reinterpret_cast<const float4*>(x) + (size_t)i * (DD / 4);
    float acc = 0.f;
    #pragma unroll 8
    for (int k4 = 0; k4 < DD / 4; ++k4) {
        float4 xv = xr[k4];
        float4 wv = *reinterpret_cast<const float4*>(&wns[k4 * 4]);
        acc = fmaf(xv.x, wv.x, acc); acc = fmaf(xv.y, wv.y, acc);
        acc = fmaf(xv.z, wv.z, acc); acc = fmaf(xv.w, wv.w, acc);
    }
    #pragma unroll 8
    for (int k4 = 0; k4 < HH / 4; ++k4) {
        float4 ev = *reinterpret_cast<const float4*>(&embs[lab][k4 * 4]);
        float4 wv = *reinterpret_cast<const float4*>(&wns[DD + k4 * 4]);
        acc = fmaf(ev.x, wv.x, acc); acc = fmaf(ev.y, wv.y, acc);
        acc = fmaf(ev.z, wv.z, acc); acc = fmaf(ev.w, wv.w, acc);
    }
    g_scores[i] = tanhf(acc + lin_b[0]);
}

// ---------------- kernel: fused per-cluster sum + final blend ----------------
// Block k handles cluster k: deterministic in-order sum, then writes out[]
// for its own members (clusters partition the index set).
__global__ void __launch_bounds__(128) k_sal(float* __restrict__ out) {
    __shared__ float red[128];
    int k = blockIdx.x;
    int len = g_len[k], off = g_off[k];
    float s = 0.f;
    for (int t = threadIdx.x; t < len; t += 128) s += g_scores[g_sorted[off + t]];
    red[threadIdx.x] = s;
    __syncthreads();
    #pragma unroll
    for (int d = 64; d >= 1; d >>= 1) {
        if (threadIdx.x < d) red[threadIdx.x] += red[threadIdx.x + d];
        __syncthreads();
    }
    float inv_sum = 1.0f / red[0];
    const float INV = 0.0625f;  // 1 / 4096^(1/3)
    for (int t = threadIdx.x; t < len; t += 128) {
        int i = g_sorted[off + t];
        float sal = g_scores[i] * inv_sum;
        float pos = fmaxf(0.5f, expf(-((float)(i + 1)) * INV));
        out[i] = 0.5f * sal + 0.5f * pos;
    }
}

// ---------------- launch ----------------
extern "C" void kernel_launch(void* const* d_in, const int* in_sizes, int n_in,
                              void* d_out, int out_size) {
    const float* x      = (const float*)d_in[0];
    const int*   labels = (const int*)d_in[1];
    const float* W_ih0  = (const float*)d_in[2];
    const float* W_hh0  = (const float*)d_in[3];
    const float* b_ih0  = (const float*)d_in[4];
    const float* b_hh0  = (const float*)d_in[5];
    const float* W_ih1  = (const float*)d_in[6];
    const float* W_hh1  = (const float*)d_in[7];
    const float* b_ih1  = (const float*)d_in[8];
    const float* b_hh1  = (const float*)d_in[9];
    const float* lin_v  = (const float*)d_in[10];
    const float* lin_g  = (const float*)d_in[11];
    const float* lin_b  = (const float*)d_in[12];
    float* out = (float*)d_out;

    k_setup<<<1, 256>>>(labels);
    k_pack<<<64, 384>>>(W_ih0);
    k_xw0<<<NN / 16, 384>>>(x, b_ih0);
    k_rec<<<128, 384>>>(W_hh0, W_ih1, W_hh1, b_ih0, b_hh0, b_ih1, b_hh1);
    k_score<<<NN / 128, 128>>>(x, labels, lin_v, lin_g, lin_b);
    k_sal<<<KK, 128>>>(out);
}

// round 6
// speedup vs baseline: 1.8391x; 1.6708x over previous
#include <cuda_runtime.h>
#include <cuda_bf16.h>

// Problem constants (fixed by the reference)
#define NN 4096
#define KK 32
#define DD 256
#define HH 128
#define GG 384   // 3*H
#define NR (NN + KK)   // h1 rows incl. one pad row per (possibly empty) cluster

typedef unsigned long long ull;

// ---------------- device scratch (no allocations allowed) ----------------
static __device__ float4 g_wih0p[64 * GG];   // W_ih0 packed [k4][g]
static __device__ float4 g_wih1p[32 * GG];   // W_ih1 packed [k4][g]
static __device__ float  g_xw0[NN * GG];     // x @ W_ih0^T + b_ih0
static __device__ float  g_xwz[GG];          // b_ih0 (zero-input row for empty clusters)
static __device__ float  g_h1[NR * HH];      // layer-0 hidden sequence
static __device__ float  g_xw1[NR * GG];     // h1 @ W_ih1^T + b_ih1
static __device__ int    g_sorted[NN];
static __device__ int    g_off[KK + 1];
static __device__ int    g_len[KK];
static __device__ float  g_emb[KK * HH];
static __device__ float  g_scores[NN];

// ---------------- helpers ----------------
static __device__ __forceinline__ ull ffma2(ull a, ull b, ull c) {
    ull d;
    asm("fma.rn.f32x2 %0, %1, %2, %3;" : "=l"(d) : "l"(a), "l"(b), "l"(c));
    return d;
}
static __device__ __forceinline__ float f2sum(ull v) {
    float a, b;
    asm("mov.b64 {%0, %1}, %2;" : "=f"(a), "=f"(b) : "l"(v));
    return a + b;
}
static __device__ __forceinline__ float ex2_(float x) {
    float y; asm("ex2.approx.f32 %0, %1;" : "=f"(y) : "f"(x)); return y;
}
static __device__ __forceinline__ float rcp_(float x) {
    float y; asm("rcp.approx.f32 %0, %1;" : "=f"(y) : "f"(x)); return y;
}
#define L2E 1.4426950408889634f
static __device__ __forceinline__ float fast_sigmoid(float x) {
    return rcp_(1.0f + ex2_(-x * L2E));
}
static __device__ __forceinline__ float fast_tanh(float x) {
    x = fminf(x, 20.0f);
    float e = ex2_(x * (2.0f * L2E));
    return (e - 1.0f) * rcp_(e + 1.0f);
}

// ---------------- kernel: cluster ordering (stable, parallel) ----------------
__global__ void k_setup(const int* __restrict__ labels) {
    __shared__ int ls[NN];
    __shared__ int cnt[8][KK];
    __shared__ int soff[8][KK];
    int t = threadIdx.x;                 // 256 threads
    for (int i = t; i < NN; i += 256) ls[i] = labels[i];
    __syncthreads();
    int w = t >> 5, k = t & 31;
    {
        int c = 0;
        const int4* p = (const int4*)(ls + w * 512);
        for (int ii = 0; ii < 128; ++ii) {
            int4 v = p[ii];
            c += (v.x == k) + (v.y == k) + (v.z == k) + (v.w == k);
        }
        cnt[w][k] = c;
    }
    __syncthreads();
    if (w == 0) {
        int tot = 0;
        #pragma unroll
        for (int s = 0; s < 8; ++s) tot += cnt[s][k];
        g_len[k] = tot;
        int v = tot;
        #pragma unroll
        for (int d = 1; d < 32; d <<= 1) {
            int y = __shfl_up_sync(0xffffffffu, v, d);
            if (k >= d) v += y;
        }
        int off = v - tot;
        g_off[k] = off;
        if (k == 31) g_off[32] = off + tot;
        int run = off;
        #pragma unroll
        for (int s = 0; s < 8; ++s) { soff[s][k] = run; run += cnt[s][k]; }
    }
    __syncthreads();
    {
        int c = soff[w][k];
        const int4* p = (const int4*)(ls + w * 512);
        for (int ii = 0; ii < 128; ++ii) {
            int4 v = p[ii];
            int b = w * 512 + ii * 4;
            if (v.x == k) g_sorted[c++] = b;
            if (v.y == k) g_sorted[c++] = b + 1;
            if (v.z == k) g_sorted[c++] = b + 2;
            if (v.w == k) g_sorted[c++] = b + 3;
        }
    }
}

// ---------------- kernel: pack input weights + zero-input row ----------------
__global__ void k_pack(const float* __restrict__ wih0, const float* __restrict__ wih1,
                       const float* __restrict__ b_ih0) {
    int b = blockIdx.x;          // 0..95
    int g = threadIdx.x;         // 0..383
    if (b < 64) {
        const float* row = wih0 + (size_t)g * DD + b * 4;
        g_wih0p[b * GG + g] = make_float4(row[0], row[1], row[2], row[3]);
        if (b == 0) g_xwz[g] = b_ih0[g];
    } else {
        int k4 = b - 64;
        const float* row = wih1 + (size_t)g * HH + k4 * 4;
        g_wih1p[k4 * GG + g] = make_float4(row[0], row[1], row[2], row[3]);
    }
}

// ---------------- kernel: xw0 = x @ W_ih0^T + b_ih0 ----------------
__global__ void __launch_bounds__(384) k_xw0(const float* __restrict__ x,
                                             const float* __restrict__ b_ih0) {
    __shared__ __align__(16) float xs[16 * DD];   // 16 KB
    int r0 = blockIdx.x * 16;
    {
        const float4* xsrc = reinterpret_cast<const float4*>(x + (size_t)r0 * DD);
        float4* xd = reinterpret_cast<float4*>(xs);
        for (int i = threadIdx.x; i < 16 * DD / 4; i += 384) xd[i] = xsrc[i];
    }
    __syncthreads();
    int g = threadIdx.x;
    ull acc[16];
    #pragma unroll
    for (int s = 0; s < 16; ++s) acc[s] = 0ull;
    const ulonglong2* W = reinterpret_cast<const ulonglong2*>(g_wih0p) + g;
    #pragma unroll 8
    for (int k4 = 0; k4 < 64; ++k4) {
        ulonglong2 w = W[k4 * GG];
        #pragma unroll
        for (int s = 0; s < 16; ++s) {
            ulonglong2 xv = *reinterpret_cast<const ulonglong2*>(&xs[s * DD + k4 * 4]);
            acc[s] = ffma2(w.x, xv.x, acc[s]);
            acc[s] = ffma2(w.y, xv.y, acc[s]);
        }
    }
    float bi = b_ih0[g];
    #pragma unroll
    for (int s = 0; s < 16; ++s)
        g_xw0[(size_t)(r0 + s) * GG + g] = f2sum(acc[s]) + bi;
}

// ---------------- kernel: xw1 = h1 @ W_ih1^T + b_ih1 (NR rows) ----------------
__global__ void __launch_bounds__(384) k_xw1(const float* __restrict__ b_ih1) {
    __shared__ __align__(16) float xs[16 * HH];   // 8 KB
    int r0 = blockIdx.x * 16;
    {
        const float4* xsrc = reinterpret_cast<const float4*>(g_h1 + (size_t)r0 * HH);
        float4* xd = reinterpret_cast<float4*>(xs);
        for (int i = threadIdx.x; i < 16 * HH / 4; i += 384) xd[i] = xsrc[i];
    }
    __syncthreads();
    int g = threadIdx.x;
    ull acc[16];
    #pragma unroll
    for (int s = 0; s < 16; ++s) acc[s] = 0ull;
    const ulonglong2* W = reinterpret_cast<const ulonglong2*>(g_wih1p) + g;
    #pragma unroll 8
    for (int k4 = 0; k4 < 32; ++k4) {
        ulonglong2 w = W[k4 * GG];
        #pragma unroll
        for (int s = 0; s < 16; ++s) {
            ulonglong2 xv = *reinterpret_cast<const ulonglong2*>(&xs[s * HH + k4 * 4]);
            acc[s] = ffma2(w.x, xv.x, acc[s]);
            acc[s] = ffma2(w.y, xv.y, acc[s]);
        }
    }
    float bi = b_ih1[g];
    #pragma unroll
    for (int s = 0; s < 16; ++s)
        g_xw1[(size_t)(r0 + s) * GG + g] = f2sum(acc[s]) + bi;
}

// ---------------- kernel: single-layer GRU recurrence, ONE CTA per cluster ----
// Thread t owns gate row t of W (384x128) fully in registers (32 ulonglong2).
// Per step: thread-private full dot product (no reduction), STS to hw, bar,
// gates on threads 0..127, bar. No cross-SM communication of any kind.
// pass 0: input = g_xw0[g_sorted[...]] rows, writes h1 sequence to g_h1.
// pass 1: input = g_xw1 rows (sequential), writes final h to g_emb.
__global__ void __launch_bounds__(384, 1) k_gru(const float* __restrict__ W,
                                                const float* __restrict__ bh,
                                                int pass) {
    __shared__ __align__(16) float h[HH];
    __shared__ float hw[GG];
    __shared__ __align__(16) float stage[64 * 132];   // 33.8 KB weight staging

    const int t = threadIdx.x;
    const int c = blockIdx.x;

    // ---- load weight row t into registers, smem-staged for coalescing
    ulonglong2 w[32];
    for (int grp = 0; grp < 6; ++grp) {
        const float4* src = reinterpret_cast<const float4*>(W + (size_t)(64 * grp) * HH);
        #pragma unroll
        for (int u = 0; u < 6; ++u) {
            int f = t + u * 384;              // float4 index within 64x128 block
            if (f < 2048) {
                int r = f >> 5, c4 = f & 31;
                *(float4*)&stage[r * 132 + c4 * 4] = src[f];
            }
        }
        __syncthreads();
        if ((t >> 6) == grp) {
            int r = t & 63;
            #pragma unroll
            for (int i = 0; i < 32; ++i)
                w[i] = *(const ulonglong2*)&stage[r * 132 + i * 4];
        }
        __syncthreads();
    }
    float bias = bh[t];
    if (t < HH) h[t] = 0.f;

    const int len = g_len[c], off = g_off[c];
    const int len_e = max(len, 1);

    // ---- input prefetch (threads 0..127 hold the 3 gate inputs for slot t)
    float xr = 0.f, xz = 0.f, xn = 0.f;
    int nidx = 0;
    if (t < HH) {
        const float* r0;
        if (pass == 0) r0 = (len > 0) ? (g_xw0 + (size_t)g_sorted[off] * GG) : g_xwz;
        else           r0 = g_xw1 + (size_t)((len > 0) ? off : (NN + c)) * GG;
        xr = r0[t]; xz = r0[HH + t]; xn = r0[2 * HH + t];
        if (pass == 0 && len > 1) nidx = g_sorted[off + 1];
    }
    __syncthreads();

    for (int it = 0; it < len_e; ++it) {
        // ---- matvec: hw[t] = dot(W_row_t, h) + bias, fully thread-private
        ull ax = 0ull, ay = 0ull;
        const ulonglong2* hp = reinterpret_cast<const ulonglong2*>(h);
        #pragma unroll
        for (int i = 0; i < 32; ++i) {
            ulonglong2 hv = hp[i];
            ax = ffma2(w[i].x, hv.x, ax);
            ay = ffma2(w[i].y, hv.y, ay);
        }
        hw[t] = f2sum(ax) + f2sum(ay) + bias;
        __syncthreads();

        // ---- gate update (threads 0..127)
        if (t < HH) {
            float r = fast_sigmoid(xr + hw[t]);
            float z = fast_sigmoid(xz + hw[HH + t]);
            float n = fast_tanh(xn + r * hw[2 * HH + t]);
            float hn = (1.0f - z) * n + z * h[t];
            h[t] = hn;
            if (pass == 0) {
                int orow = (len > 0) ? (off + it) : (NN + c);
                g_h1[(size_t)orow * HH + t] = hn;
            }
            // prefetch next step's input row
            if (it + 1 < len_e) {
                const float* rn;
                if (pass == 0) rn = g_xw0 + (size_t)nidx * GG;
                else           rn = g_xw1 + (size_t)(off + it + 1) * GG;
                xr = rn[t]; xz = rn[HH + t]; xn = rn[2 * HH + t];
                if (pass == 0 && it + 2 < len) nidx = g_sorted[off + it + 2];
            }
        }
        __syncthreads();
    }

    if (pass == 1 && t < HH) g_emb[c * HH + t] = h[t];
}

// ---------------- kernel: per-sentence tanh scores (weight-norm fused) -------
__global__ void __launch_bounds__(128) k_score(const float* __restrict__ x,
                                               const int* __restrict__ labels,
                                               const float* __restrict__ lin_v,
                                               const float* __restrict__ lin_g,
                                               const float* __restrict__ lin_b) {
    __shared__ __align__(16) float wns[GG];
    __shared__ __align__(16) float embs[KK][132];  // padded
    __shared__ float redw[4];
    int t = threadIdx.x;
    float v0 = lin_v[t], v1 = lin_v[HH + t], v2 = lin_v[2 * HH + t];
    float ss = v0 * v0 + v1 * v1 + v2 * v2;
    #pragma unroll
    for (int d = 16; d >= 1; d >>= 1) ss += __shfl_xor_sync(0xffffffffu, ss, d);
    if ((t & 31) == 0) redw[t >> 5] = ss;
    __syncthreads();
    float scale = lin_g[0] / sqrtf(redw[0] + redw[1] + redw[2] + redw[3]);
    wns[t] = v0 * scale; wns[HH + t] = v1 * scale; wns[2 * HH + t] = v2 * scale;
    for (int i = t; i < KK * HH; i += 128) embs[i >> 7][i & 127] = g_emb[i];
    __syncthreads();
    int i = blockIdx.x * 128 + t;
    int lab = labels[i];
    const float4* xr = reinterpret_cast<const float4*>(x) + (size_t)i * (DD / 4);
    float acc = 0.f;
    #pragma unroll 8
    for (int k4 = 0; k4 < DD / 4; ++k4) {
        float4 xv = xr[k4];
        float4 wv = *reinterpret_cast<const float4*>(&wns[k4 * 4]);
        acc = fmaf(xv.x, wv.x, acc); acc = fmaf(xv.y, wv.y, acc);
        acc = fmaf(xv.z, wv.z, acc); acc = fmaf(xv.w, wv.w, acc);
    }
    #pragma unroll 8
    for (int k4 = 0; k4 < HH / 4; ++k4) {
        float4 ev = *reinterpret_cast<const float4*>(&embs[lab][k4 * 4]);
        float4 wv = *reinterpret_cast<const float4*>(&wns[DD + k4 * 4]);
        acc = fmaf(ev.x, wv.x, acc); acc = fmaf(ev.y, wv.y, acc);
        acc = fmaf(ev.z, wv.z, acc); acc = fmaf(ev.w, wv.w, acc);
    }
    g_scores[i] = tanhf(acc + lin_b[0]);
}

// ---------------- kernel: fused per-cluster sum + final blend -----------------
__global__ void __launch_bounds__(128) k_sal(float* __restrict__ out) {
    __shared__ float red[128];
    int k = blockIdx.x;
    int len = g_len[k], off = g_off[k];
    float s = 0.f;
    for (int t = threadIdx.x; t < len; t += 128) s += g_scores[g_sorted[off + t]];
    red[threadIdx.x] = s;
    __syncthreads();
    #pragma unroll
    for (int d = 64; d >= 1; d >>= 1) {
        if (threadIdx.x < d) red[threadIdx.x] += red[threadIdx.x + d];
        __syncthreads();
    }
    float inv_sum = 1.0f / red[0];
    const float INV = 0.0625f;  // 1 / 4096^(1/3)
    for (int t = threadIdx.x; t < len; t += 128) {
        int i = g_sorted[off + t];
        float sal = g_scores[i] * inv_sum;
        float pos = fmaxf(0.5f, expf(-((float)(i + 1)) * INV));
        out[i] = 0.5f * sal + 0.5f * pos;
    }
}

// ---------------- launch ----------------
extern "C" void kernel_launch(void* const* d_in, const int* in_sizes, int n_in,
                              void* d_out, int out_size) {
    const float* x      = (const float*)d_in[0];
    const int*   labels = (const int*)d_in[1];
    const float* W_ih0  = (const float*)d_in[2];
    const float* W_hh0  = (const float*)d_in[3];
    const float* b_ih0  = (const float*)d_in[4];
    const float* b_hh0  = (const float*)d_in[5];
    const float* W_ih1  = (const float*)d_in[6];
    const float* W_hh1  = (const float*)d_in[7];
    const float* b_ih1  = (const float*)d_in[8];
    const float* b_hh1  = (const float*)d_in[9];
    const float* lin_v  = (const float*)d_in[10];
    const float* lin_g  = (const float*)d_in[11];
    const float* lin_b  = (const float*)d_in[12];
    float* out = (float*)d_out;

    k_setup<<<1, 256>>>(labels);
    k_pack<<<96, 384>>>(W_ih0, W_ih1, b_ih0);
    k_xw0<<<NN / 16, 384>>>(x, b_ih0);
    k_gru<<<KK, 384>>>(W_hh0, b_hh0, 0);
    k_xw1<<<NR / 16, 384>>>(b_ih1);
    k_gru<<<KK, 384>>>(W_hh1, b_hh1, 1);
    k_score<<<NN / 128, 128>>>(x, labels, lin_v, lin_g, lin_b);
    k_sal<<<KK, 128>>>(out);
}